// round 16
// baseline (speedup 1.0000x reference)
#include <cuda_runtime.h>
#include <cstdint>

// Problem constants
#define BB 32
#define SS 2048
#define HH 32
#define NOPE 128
#define VD 128
#define HID 4096
#define QKVN 12288              // 4096 q (compact nope) + 4096 k + 4096 v
#define SCALE 0.08838834764831843f   // 128^-0.5

#define NCHUNK 8
#define CHUNK 256

#define SPLIT1 16               // GEMM1 split-K
#define SPLIT2 16               // GEMM2 split-K

// ---------------- scratch (static device globals; no runtime alloc) -------------
__device__ float g_p1[(size_t)SPLIT1 * 32u * 12288u];   // GEMM1 partials (25 MB)
__device__ float g_qkv[32u * 12288u];            // fused q/k/v projections
__device__ float g_pm[1024 * NCHUNK];            // per-(b,h,chunk) running max
__device__ float g_pl[1024 * NCHUNK];            // per-(b,h,chunk) exp-sum
__device__ float g_pacc[1024 * NCHUNK * 128];    // per-chunk weighted V (4 MB)
__device__ float g_attn[32u * 4096u];            // attention output [B][H*VD]
__device__ float g_p2[(size_t)SPLIT2 * 32u * 4096u];    // GEMM2 partials (8.4 MB)

// ---------------- prep kernels (also place gemm1 in ncu's profiled slot 4) ------
__global__ void zero_pl_kernel() { g_pl[blockIdx.x * 256 + threadIdx.x] = 0.f; }
__global__ void zero_pm0_kernel() { g_pm[blockIdx.x * 256 + threadIdx.x] = -1e30f; }
__global__ void zero_pm1_kernel() {
    g_pm[4096 + blockIdx.x * 256 + threadIdx.x] = -1e30f;
}

// bf16x2 pack: result = {hi: b, lo: a}  (first PTX source -> high half)
__device__ __forceinline__ unsigned bf16x2(float hi, float lo) {
    unsigned d;
    asm("cvt.rn.bf16x2.f32 %0, %1, %2;" : "=r"(d) : "f"(hi), "f"(lo));
    return d;
}
// split (x0, x1) -> packed hi bf16x2 {x1,x0} and packed lo residual bf16x2
__device__ __forceinline__ void split2(float x0, float x1, unsigned& hi,
                                       unsigned& lo) {
    hi = bf16x2(x1, x0);
    float h0 = __uint_as_float(hi << 16);
    float h1 = __uint_as_float(hi & 0xFFFF0000u);
    lo = bf16x2(x1 - h1, x0 - h0);
}
// mma.sync m16n8k16 bf16 -> f32 accumulate in place
#define MMA16816(D, Av, Bv)                                                  \
    asm volatile(                                                            \
        "mma.sync.aligned.m16n8k16.row.col.f32.bf16.bf16.f32 "               \
        "{%0,%1,%2,%3}, {%4,%5,%6,%7}, {%8,%9}, {%0,%1,%2,%3};"              \
        : "+f"(D[0]), "+f"(D[1]), "+f"(D[2]), "+f"(D[3])                     \
        : "r"(Av.x), "r"(Av.y), "r"(Av.z), "r"(Av.w), "r"(Bv.x), "r"(Bv.y))

// =====================================================================
// GEMM v9 (tensor-core, double-buffered fragments): C = A @ W^T, split-K.
// v8 was PHASE-SERIALIZED: staging (cvt+STS) ran to a barrier before any
// MMA issued -> tensor 28%, issue 24%, nothing saturated. v9 double-
// buffers the fragment smem: iteration ks stages step ks+1 into buf^1,
// prefetches LDGs for ks+2, and runs the 48 MMAs on buf -- one barrier
// per step, staging work issues under the tensor-pipe shadow.
// bf16 hi/lo split x 3 products, fp32 accum (rel err ~1e-5); fragment
// lane maps verbatim from verified v7/v8.
// Block: 256 thr = 8 warps; tile M=32 x BN=256 x BK=32 per step.
// MODE 0: W = fused Wq(nope-compact rows)+Wkv virtual rows, -> g_p1.
// MODE 1: W = Wo, A = g_attn, -> g_p2.
// =====================================================================
template <int MODE>
__global__ void __launch_bounds__(256, 2) gemm_kernel(
    const float* __restrict__ A, const float* __restrict__ W0,
    const float* __restrict__ W1, int N, int ksteps, float* __restrict__ part) {
    // dyn smem: Wf[2][8192] u32 (64 KB) + Af[2][1024] u32 (8 KB)
    extern __shared__ __align__(16) unsigned dsm[];
    unsigned* WfB[2] = {dsm, dsm + 8192};
    unsigned* AfB[2] = {dsm + 16384, dsm + 16384 + 1024};

    const int t = threadIdx.x;
    const int w = t >> 5, l = t & 31;
    const int n0 = blockIdx.x * 256;
    const int kbase = blockIdx.y * (ksteps * 32);
    const float* Ap = (MODE == 0) ? A : g_attn;

    // ---- staging assignments (fixed n/m, k advances) ----
    const int wn = t >> 3;
    const int wkk = (t & 7) * 4;
    const float* wptr[8];
#pragma unroll
    for (int p = 0; p < 8; p++) {
        int n = n0 + p * 32 + wn;
        const float* row;
        if (MODE == 0)
            row = (n < 4096) ? W0 + (size_t)((n >> 7) * 192 + (n & 127)) * HID
                             : W1 + (size_t)(n - 4096) * HID;
        else
            row = W0 + (size_t)n * HID;
        wptr[p] = row + kbase + wkk;
    }
    const int wk16 = wkk >> 4;
    const int wbreg = (wkk & 15) >> 3;
    const int wpidx = (wkk & 7) >> 1;
    const int am = t >> 3;
    const float* aptr = Ap + (size_t)am * HID + kbase + wkk;
    const int amt = am >> 4;
    const int aareg = ((am >> 3) & 1) + 2 * wbreg;
    const int alane = 4 * (am & 7) + wpidx;

    float acc[2][4][4];   // [mt][j][c0..c3]
#pragma unroll
    for (int i = 0; i < 2; i++)
#pragma unroll
        for (int j = 0; j < 4; j++)
#pragma unroll
            for (int c = 0; c < 4; c++) acc[i][j][c] = 0.f;

    float4 wv[8], av;   // prefetched step (regs for the NEXT stage call)

    // stage the prefetched step's fragments into buffer b
    auto stage = [&](int b) {
        unsigned* Wf = WfB[b];
        unsigned* Af = AfB[b];
#pragma unroll
        for (int p = 0; p < 8; p++) {
            unsigned hi0, lo0, hi1, lo1;
            split2(wv[p].x, wv[p].y, hi0, lo0);
            split2(wv[p].z, wv[p].w, hi1, lo1);
            int n = p * 32 + wn;
            int nt = n >> 3;
            int lane0 = 4 * (n & 7) + wpidx;
            unsigned* baseh = Wf + (((nt * 2 + wk16) * 2 + 0) * 32) * 2 + wbreg;
            unsigned* basel = Wf + (((nt * 2 + wk16) * 2 + 1) * 32) * 2 + wbreg;
            baseh[lane0 * 2] = hi0;
            baseh[(lane0 + 1) * 2] = hi1;
            basel[lane0 * 2] = lo0;
            basel[(lane0 + 1) * 2] = lo1;
        }
        unsigned hi0, lo0, hi1, lo1;
        split2(av.x, av.y, hi0, lo0);
        split2(av.z, av.w, hi1, lo1);
        unsigned* baseh = Af + (((amt * 2 + wk16) * 2 + 0) * 32) * 4 + aareg;
        unsigned* basel = Af + (((amt * 2 + wk16) * 2 + 1) * 32) * 4 + aareg;
        baseh[alane * 4] = hi0;
        baseh[(alane + 1) * 4] = hi1;
        basel[alane * 4] = lo0;
        basel[(alane + 1) * 4] = lo1;
    };
    auto prefetch = [&](int step) {
        const int kofs = step * 32;
#pragma unroll
        for (int p = 0; p < 8; p++) wv[p] = *(const float4*)(wptr[p] + kofs);
        av = *(const float4*)(aptr + kofs);
    };

    // prologue: stage step 0 into buf 0, prefetch step 1
    prefetch(0);
    stage(0);
    prefetch(1);
    __syncthreads();

    for (int ks = 0; ks < ksteps; ks++) {
        const int buf = ks & 1;
        // stage step ks+1 into buf^1 (overlaps with this step's MMAs)
        if (ks + 1 < ksteps) {
            stage(buf ^ 1);
            if (ks + 2 < ksteps) prefetch(ks + 2);
        }
        // ---- compute: 2 k16 x (2 mt x 4 nt x 3 products) = 48 MMA ----
        unsigned* Wf = WfB[buf];
        unsigned* Af = AfB[buf];
#pragma unroll
        for (int k16 = 0; k16 < 2; k16++) {
            uint4 Ah0 = *(const uint4*)(Af + (((0 * 2 + k16) * 2 + 0) * 32 + l) * 4);
            uint4 Al0 = *(const uint4*)(Af + (((0 * 2 + k16) * 2 + 1) * 32 + l) * 4);
            uint4 Ah1 = *(const uint4*)(Af + (((1 * 2 + k16) * 2 + 0) * 32 + l) * 4);
            uint4 Al1 = *(const uint4*)(Af + (((1 * 2 + k16) * 2 + 1) * 32 + l) * 4);
#pragma unroll
            for (int j = 0; j < 4; j++) {
                const int nt = 4 * w + j;
                uint2 Bh = *(const uint2*)(Wf + (((nt * 2 + k16) * 2 + 0) * 32 + l) * 2);
                uint2 Bl = *(const uint2*)(Wf + (((nt * 2 + k16) * 2 + 1) * 32 + l) * 2);
                MMA16816(acc[0][j], Ah0, Bh);
                MMA16816(acc[1][j], Ah1, Bh);
                MMA16816(acc[0][j], Al0, Bh);
                MMA16816(acc[1][j], Al1, Bh);
                MMA16816(acc[0][j], Ah0, Bl);
                MMA16816(acc[1][j], Ah1, Bl);
            }
        }
        __syncthreads();   // buf consumed; next iter may overwrite it
    }

    // ---- epilogue: C lane map: rows l/4, l/4+8; cols 2(l%4)+{0,1} ----
    float* pbase = part + (size_t)blockIdx.y * 32 * N;
#pragma unroll
    for (int mt = 0; mt < 2; mt++)
#pragma unroll
        for (int j = 0; j < 4; j++) {
            int col = n0 + w * 32 + j * 8 + 2 * (l & 3);
            int r0 = mt * 16 + (l >> 2);
            *(float2*)(pbase + (size_t)r0 * N + col) =
                make_float2(acc[mt][j][0], acc[mt][j][1]);
            *(float2*)(pbase + (size_t)(r0 + 8) * N + col) =
                make_float2(acc[mt][j][2], acc[mt][j][3]);
        }
}

// sum the SPLIT1 GEMM1 split-K partials -> g_qkv
__global__ void reduce_qkv_kernel() {
    int i = blockIdx.x * 256 + threadIdx.x;   // 393216 total
    float s = 0.f;
#pragma unroll
    for (int c = 0; c < SPLIT1; c++) s += g_p1[(size_t)c * 393216 + i];
    g_qkv[i] = s;
}

// =====================================================================
// Flash-decoding attention partial (AT THE MEMORY WALL: 80% DRAM, ~96%
// of the 6.35 TB/s LTS cap — unchanged). One block per (b,h,chunk).
// =====================================================================
__global__ void __launch_bounds__(256) attn_partial_kernel(
    const float* __restrict__ k_cache, const float* __restrict__ v_cache,
    const int* __restrict__ positions) {
    const int bh = blockIdx.x;
    const int c = blockIdx.y;
    const int b = bh >> 5, h = bh & 31;
    const int t = threadIdx.x, lane = t & 31, w = t >> 5;
    const int pos = positions[b];
    const int L = pos + 1;
    const int s0 = c * CHUNK;
    const int len = min(CHUNK, L - s0);
    const int pidx = bh * NCHUNK + c;
    if (len <= 0) return;   // g_pl pre-zeroed by prep kernel

    __shared__ float sc[CHUNK];
    __shared__ float red[256];
    __shared__ float redw[8];
    __shared__ float s_m, s_l;

    const float* qb = g_qkv + b * QKVN + h * 128;
    const float4 q4 = *(const float4*)(qb + lane * 4);
    const float* knew = g_qkv + b * QKVN + 4096 + h * 128;
    const float* kbasep = k_cache + (size_t)b * SS * (HH * 128) + h * 128;

    for (int sl = 4 * w; sl < len; sl += 32) {
        float4 kv[4];
        float dd[4];
#pragma unroll
        for (int i = 0; i < 4; i++) {
            int sli = sl + i;
            int s = s0 + sli;
            const float* kp = (sli < len)
                                  ? ((s == pos) ? knew
                                                : (kbasep + (size_t)s * 4096))
                                  : knew;   // safe dummy
            kv[i] = *(const float4*)(kp + lane * 4);
        }
#pragma unroll
        for (int i = 0; i < 4; i++)
            dd[i] = kv[i].x * q4.x + kv[i].y * q4.y + kv[i].z * q4.z +
                    kv[i].w * q4.w;
#pragma unroll
        for (int o = 16; o; o >>= 1) {
#pragma unroll
            for (int i = 0; i < 4; i++)
                dd[i] += __shfl_xor_sync(0xffffffffu, dd[i], o);
        }
        if (lane == 0) {
#pragma unroll
            for (int i = 0; i < 4; i++)
                if (sl + i < len) sc[sl + i] = dd[i] * SCALE;
        }
    }
    __syncthreads();

    float lm = (t < len) ? sc[t] : -1e30f;
#pragma unroll
    for (int o = 16; o; o >>= 1) lm = fmaxf(lm, __shfl_xor_sync(0xffffffffu, lm, o));
    if (lane == 0) redw[w] = lm;
    __syncthreads();
    if (t == 0) {
        float m = redw[0];
#pragma unroll
        for (int i = 1; i < 8; i++) m = fmaxf(m, redw[i]);
        s_m = m;
    }
    __syncthreads();
    const float m = s_m;
    float ls = 0.f;
    if (t < len) {
        float p = __expf(sc[t] - m);
        sc[t] = p;
        ls = p;
    }
#pragma unroll
    for (int o = 16; o; o >>= 1) ls += __shfl_xor_sync(0xffffffffu, ls, o);
    if (lane == 0) redw[w] = ls;
    __syncthreads();
    if (t == 0) {
        float l = 0.f;
#pragma unroll
        for (int i = 0; i < 8; i++) l += redw[i];
        s_l = l;
    }
    __syncthreads();

    const float* vnew = g_qkv + b * QKVN + 8192 + h * 128;
    const float* vbasep = v_cache + (size_t)b * SS * (HH * 128) + h * 128;
    const int d = t & 127;
    const int half = t >> 7;
    float acc = 0.f;
#pragma unroll 8
    for (int sl = half; sl < len; sl += 2) {
        int s = s0 + sl;
        const float* vr = (s == pos) ? vnew : (vbasep + (size_t)s * 4096);
        acc += sc[sl] * vr[d];
    }
    red[t] = acc;
    __syncthreads();
    if (t < 128) g_pacc[(size_t)pidx * 128 + t] = red[t] + red[t + 128];
    if (t == 0) {
        g_pm[pidx] = m;
        g_pl[pidx] = s_l;
    }
}

// combine the <=8 chunk partials per (b,h) -> g_attn[b][h*VD+d]
__global__ void __launch_bounds__(128) attn_combine_kernel() {
    const int bh = blockIdx.x;
    const int d = threadIdx.x;
    float M = -1e30f;
#pragma unroll
    for (int c = 0; c < NCHUNK; c++) {
        float l = g_pl[bh * NCHUNK + c];
        if (l > 0.f) M = fmaxf(M, g_pm[bh * NCHUNK + c]);
    }
    float L = 0.f, o = 0.f;
#pragma unroll
    for (int c = 0; c < NCHUNK; c++) {
        float l = g_pl[bh * NCHUNK + c];
        if (l > 0.f) {
            float wgt = __expf(g_pm[bh * NCHUNK + c] - M);
            L += l * wgt;
            o += g_pacc[(size_t)(bh * NCHUNK + c) * 128 + d] * wgt;
        }
    }
    const int b = bh >> 5, h = bh & 31;
    g_attn[b * 4096 + h * 128 + d] = o / L;
}

// sum the SPLIT2 GEMM2 split-K partials -> final output
__global__ void reduce_out_kernel(float* __restrict__ out) {
    int i = blockIdx.x * 256 + threadIdx.x;   // 131072 total
    float s = 0.f;
#pragma unroll
    for (int c = 0; c < SPLIT2; c++) s += g_p2[(size_t)c * 131072 + i];
    out[i] = s;
}

extern "C" void kernel_launch(void* const* d_in, const int* in_sizes, int n_in,
                              void* d_out, int out_size) {
    const float* hs = (const float*)d_in[0];
    const int* positions = (const int*)d_in[1];
    const float* k_cache = (const float*)d_in[2];
    const float* v_cache = (const float*)d_in[3];
    const float* Wq = (const float*)d_in[4];
    const float* Wkv = (const float*)d_in[5];
    const float* Wo = (const float*)d_in[6];
    float* out = (float*)d_out;

    float* p1;
    cudaGetSymbolAddress((void**)&p1, g_p1);
    float* p2;
    cudaGetSymbolAddress((void**)&p2, g_p2);

    const int SMEM_BYTES = (2 * 8192 + 2 * 1024) * 4;   // 73728
    cudaFuncSetAttribute(gemm_kernel<0>,
                         cudaFuncAttributeMaxDynamicSharedMemorySize, SMEM_BYTES);
    cudaFuncSetAttribute(gemm_kernel<1>,
                         cudaFuncAttributeMaxDynamicSharedMemorySize, SMEM_BYTES);

    // prep (slots 1-3): zero attention stats; puts gemm1 in profiled slot 4
    zero_pl_kernel<<<32, 256>>>();
    zero_pm0_kernel<<<16, 256>>>();
    zero_pm1_kernel<<<16, 256>>>();
    // 1) fused q(nope)/k/v projection: 48 N-tiles x split-K 16 (8 k-steps)
    gemm_kernel<0><<<dim3(48, SPLIT1), 256, SMEM_BYTES>>>(hs, Wq, Wkv, QKVN, 8,
                                                          p1);
    reduce_qkv_kernel<<<1536, 256>>>();
    // 2) flash-decoding attention partials
    attn_partial_kernel<<<dim3(1024, NCHUNK), 256>>>(k_cache, v_cache, positions);
    attn_combine_kernel<<<1024, 128>>>();
    // 3) output projection: 16 N-tiles x split-K 16 (8 k-steps)
    gemm_kernel<1><<<dim3(16, SPLIT2), 256, SMEM_BYTES>>>(nullptr, Wo, nullptr,
                                                          HID, 8, p2);
    reduce_out_kernel<<<512, 256>>>(out);
}

// round 17
// speedup vs baseline: 1.0416x; 1.0416x over previous
#include <cuda_runtime.h>
#include <cstdint>

// Problem constants
#define BB 32
#define SS 2048
#define HH 32
#define NOPE 128
#define VD 128
#define HID 4096
#define QKVN 12288              // 4096 q (compact nope) + 4096 k + 4096 v
#define SCALE 0.08838834764831843f   // 128^-0.5

#define NCHUNK 8
#define CHUNK 256

#define SPLIT1 16               // GEMM1 split-K
#define SPLIT2 16               // GEMM2 split-K

// ---------------- scratch (static device globals; no runtime alloc) -------------
__device__ float g_p1[(size_t)SPLIT1 * 32u * 12288u];   // GEMM1 partials (25 MB)
__device__ float g_qkv[32u * 12288u];            // fused q/k/v projections
__device__ float g_pm[1024 * NCHUNK];            // per-(b,h,chunk) running max
__device__ float g_pl[1024 * NCHUNK];            // per-(b,h,chunk) exp-sum
__device__ float g_pacc[1024 * NCHUNK * 128];    // per-chunk weighted V (4 MB)
__device__ float g_attn[32u * 4096u];            // attention output [B][H*VD]
__device__ float g_p2[(size_t)SPLIT2 * 32u * 4096u];    // GEMM2 partials (8.4 MB)

// ---------------- prep kernel (single launch; attn lands in profiled slot 4) ----
__global__ void prep_kernel() {
    int i = blockIdx.x * 256 + threadIdx.x;   // 8192 entries
    g_pl[i] = 0.f;
    g_pm[i] = -1e30f;
}

// bf16x2 pack: result = {hi: b, lo: a}  (first PTX source -> high half)
__device__ __forceinline__ unsigned bf16x2(float hi, float lo) {
    unsigned d;
    asm("cvt.rn.bf16x2.f32 %0, %1, %2;" : "=r"(d) : "f"(hi), "f"(lo));
    return d;
}
// split (x0, x1) -> packed hi bf16x2 {x1,x0} and packed lo residual bf16x2
__device__ __forceinline__ void split2(float x0, float x1, unsigned& hi,
                                       unsigned& lo) {
    hi = bf16x2(x1, x0);
    float h0 = __uint_as_float(hi << 16);
    float h1 = __uint_as_float(hi & 0xFFFF0000u);
    lo = bf16x2(x1 - h1, x0 - h0);
}
// mma.sync m16n8k16 bf16 -> f32 accumulate in place
#define MMA16816(D, Av, Bv)                                                  \
    asm volatile(                                                            \
        "mma.sync.aligned.m16n8k16.row.col.f32.bf16.bf16.f32 "               \
        "{%0,%1,%2,%3}, {%4,%5,%6,%7}, {%8,%9}, {%0,%1,%2,%3};"              \
        : "+f"(D[0]), "+f"(D[1]), "+f"(D[2]), "+f"(D[3])                     \
        : "r"(Av.x), "r"(Av.y), "r"(Av.z), "r"(Av.w), "r"(Bv.x), "r"(Bv.y))

// =====================================================================
// GEMM v8 (tensor-core, wide-N + pipelined) — BEST MEASURED (58.8us G1).
// v9's double-buffer regressed (reg-capped, issue fell); restored v8.
// bf16 hi/lo split x 3 products, fp32 accum (rel err ~1e-5), fragment-
// ordered smem (verified lane maps); BN=256, nt=4/warp (1.33 wf/MMA);
// register prefetch of next k-step's W/A under the 48-MMA window.
// Block: 256 thr = 8 warps; tile M=32 x BN=256 x BK=32 per step.
// MODE 0: W = fused Wq(nope-compact rows)+Wkv virtual rows, -> g_p1.
// MODE 1: W = Wo, A = g_attn, -> g_p2.
// =====================================================================
template <int MODE>
__global__ void __launch_bounds__(256, 2) gemm_kernel(
    const float* __restrict__ A, const float* __restrict__ W0,
    const float* __restrict__ W1, int N, int ksteps, float* __restrict__ part) {
    // Wf[nt(32)][k16(2)][hl(2)][lane(32)][breg(2)] u32 = 8192 u32 (32 KB)
    // Af[mt(2)][k16(2)][hl(2)][lane(32)][areg(4)] u32 = 1024 u32 (4 KB)
    __shared__ __align__(16) unsigned Wf[8192];
    __shared__ __align__(16) unsigned Af[1024];

    const int t = threadIdx.x;
    const int w = t >> 5, l = t & 31;
    const int n0 = blockIdx.x * 256;
    const int kbase = blockIdx.y * (ksteps * 32);
    const float* Ap = (MODE == 0) ? A : g_attn;

    // ---- staging assignments (fixed n/m, k advances) ----
    const int wn = t >> 3;
    const int wkk = (t & 7) * 4;
    const float* wptr[8];
#pragma unroll
    for (int p = 0; p < 8; p++) {
        int n = n0 + p * 32 + wn;
        const float* row;
        if (MODE == 0)
            row = (n < 4096) ? W0 + (size_t)((n >> 7) * 192 + (n & 127)) * HID
                             : W1 + (size_t)(n - 4096) * HID;
        else
            row = W0 + (size_t)n * HID;
        wptr[p] = row + kbase + wkk;
    }
    const int wk16 = wkk >> 4;
    const int wbreg = (wkk & 15) >> 3;
    const int wpidx = (wkk & 7) >> 1;
    const int am = t >> 3;
    const float* aptr = Ap + (size_t)am * HID + kbase + wkk;
    const int amt = am >> 4;
    const int aareg = ((am >> 3) & 1) + 2 * wbreg;
    const int alane = 4 * (am & 7) + wpidx;

    float acc[2][4][4];   // [mt][j][c0..c3]
#pragma unroll
    for (int i = 0; i < 2; i++)
#pragma unroll
        for (int j = 0; j < 4; j++)
#pragma unroll
            for (int c = 0; c < 4; c++) acc[i][j][c] = 0.f;

    // prologue prefetch (step 0)
    float4 wv[8], av;
#pragma unroll
    for (int p = 0; p < 8; p++) wv[p] = *(const float4*)wptr[p];
    av = *(const float4*)aptr;

    for (int ks = 0; ks < ksteps; ks++) {
        __syncthreads();   // previous compute done before overwriting frags

        // ---- stage W from prefetched regs: convert + fragment-ordered STS ----
#pragma unroll
        for (int p = 0; p < 8; p++) {
            unsigned hi0, lo0, hi1, lo1;
            split2(wv[p].x, wv[p].y, hi0, lo0);
            split2(wv[p].z, wv[p].w, hi1, lo1);
            int n = p * 32 + wn;
            int nt = n >> 3;
            int lane0 = 4 * (n & 7) + wpidx;
            unsigned* baseh = Wf + (((nt * 2 + wk16) * 2 + 0) * 32) * 2 + wbreg;
            unsigned* basel = Wf + (((nt * 2 + wk16) * 2 + 1) * 32) * 2 + wbreg;
            baseh[lane0 * 2] = hi0;
            baseh[(lane0 + 1) * 2] = hi1;
            basel[lane0 * 2] = lo0;
            basel[(lane0 + 1) * 2] = lo1;
        }
        // ---- stage A ----
        {
            unsigned hi0, lo0, hi1, lo1;
            split2(av.x, av.y, hi0, lo0);
            split2(av.z, av.w, hi1, lo1);
            unsigned* baseh = Af + (((amt * 2 + wk16) * 2 + 0) * 32) * 4 + aareg;
            unsigned* basel = Af + (((amt * 2 + wk16) * 2 + 1) * 32) * 4 + aareg;
            baseh[alane * 4] = hi0;
            baseh[(alane + 1) * 4] = hi1;
            basel[alane * 4] = lo0;
            basel[(alane + 1) * 4] = lo1;
        }
        // ---- prefetch next step (hidden under compute) ----
        if (ks + 1 < ksteps) {
            const int kofs = (ks + 1) * 32;
#pragma unroll
            for (int p = 0; p < 8; p++)
                wv[p] = *(const float4*)(wptr[p] + kofs);
            av = *(const float4*)(aptr + kofs);
        }
        __syncthreads();

        // ---- compute: 2 k16 x (2 mt x 4 nt x 3 products) = 48 MMA ----
#pragma unroll
        for (int k16 = 0; k16 < 2; k16++) {
            uint4 Ah0 = *(const uint4*)(Af + (((0 * 2 + k16) * 2 + 0) * 32 + l) * 4);
            uint4 Al0 = *(const uint4*)(Af + (((0 * 2 + k16) * 2 + 1) * 32 + l) * 4);
            uint4 Ah1 = *(const uint4*)(Af + (((1 * 2 + k16) * 2 + 0) * 32 + l) * 4);
            uint4 Al1 = *(const uint4*)(Af + (((1 * 2 + k16) * 2 + 1) * 32 + l) * 4);
#pragma unroll
            for (int j = 0; j < 4; j++) {
                const int nt = 4 * w + j;
                uint2 Bh = *(const uint2*)(Wf + (((nt * 2 + k16) * 2 + 0) * 32 + l) * 2);
                uint2 Bl = *(const uint2*)(Wf + (((nt * 2 + k16) * 2 + 1) * 32 + l) * 2);
                MMA16816(acc[0][j], Ah0, Bh);
                MMA16816(acc[1][j], Ah1, Bh);
                MMA16816(acc[0][j], Al0, Bh);
                MMA16816(acc[1][j], Al1, Bh);
                MMA16816(acc[0][j], Ah0, Bl);
                MMA16816(acc[1][j], Ah1, Bl);
            }
        }
    }

    // ---- epilogue: C lane map: rows l/4, l/4+8; cols 2(l%4)+{0,1} ----
    float* pbase = part + (size_t)blockIdx.y * 32 * N;
#pragma unroll
    for (int mt = 0; mt < 2; mt++)
#pragma unroll
        for (int j = 0; j < 4; j++) {
            int col = n0 + w * 32 + j * 8 + 2 * (l & 3);
            int r0 = mt * 16 + (l >> 2);
            *(float2*)(pbase + (size_t)r0 * N + col) =
                make_float2(acc[mt][j][0], acc[mt][j][1]);
            *(float2*)(pbase + (size_t)(r0 + 8) * N + col) =
                make_float2(acc[mt][j][2], acc[mt][j][3]);
        }
}

// sum the SPLIT1 GEMM1 split-K partials -> g_qkv (float4 vectorized)
__global__ void reduce_qkv_kernel() {
    int i = blockIdx.x * 256 + threadIdx.x;   // 98304 float4s
    const float4* p = (const float4*)g_p1;
    float4 s = p[i];
#pragma unroll
    for (int c = 1; c < SPLIT1; c++) {
        float4 v = p[(size_t)c * 98304 + i];
        s.x += v.x;
        s.y += v.y;
        s.z += v.z;
        s.w += v.w;
    }
    ((float4*)g_qkv)[i] = s;
}

// =====================================================================
// Flash-decoding attention partial (AT THE MEMORY WALL: 80% DRAM, ~96%
// of the 6.35 TB/s LTS cap — unchanged). One block per (b,h,chunk).
// =====================================================================
__global__ void __launch_bounds__(256) attn_partial_kernel(
    const float* __restrict__ k_cache, const float* __restrict__ v_cache,
    const int* __restrict__ positions) {
    const int bh = blockIdx.x;
    const int c = blockIdx.y;
    const int b = bh >> 5, h = bh & 31;
    const int t = threadIdx.x, lane = t & 31, w = t >> 5;
    const int pos = positions[b];
    const int L = pos + 1;
    const int s0 = c * CHUNK;
    const int len = min(CHUNK, L - s0);
    const int pidx = bh * NCHUNK + c;
    if (len <= 0) return;   // g_pl pre-zeroed by prep kernel

    __shared__ float sc[CHUNK];
    __shared__ float red[256];
    __shared__ float redw[8];
    __shared__ float s_m, s_l;

    const float* qb = g_qkv + b * QKVN + h * 128;
    const float4 q4 = *(const float4*)(qb + lane * 4);
    const float* knew = g_qkv + b * QKVN + 4096 + h * 128;
    const float* kbasep = k_cache + (size_t)b * SS * (HH * 128) + h * 128;

    for (int sl = 4 * w; sl < len; sl += 32) {
        float4 kv[4];
        float dd[4];
#pragma unroll
        for (int i = 0; i < 4; i++) {
            int sli = sl + i;
            int s = s0 + sli;
            const float* kp = (sli < len)
                                  ? ((s == pos) ? knew
                                                : (kbasep + (size_t)s * 4096))
                                  : knew;   // safe dummy
            kv[i] = *(const float4*)(kp + lane * 4);
        }
#pragma unroll
        for (int i = 0; i < 4; i++)
            dd[i] = kv[i].x * q4.x + kv[i].y * q4.y + kv[i].z * q4.z +
                    kv[i].w * q4.w;
#pragma unroll
        for (int o = 16; o; o >>= 1) {
#pragma unroll
            for (int i = 0; i < 4; i++)
                dd[i] += __shfl_xor_sync(0xffffffffu, dd[i], o);
        }
        if (lane == 0) {
#pragma unroll
            for (int i = 0; i < 4; i++)
                if (sl + i < len) sc[sl + i] = dd[i] * SCALE;
        }
    }
    __syncthreads();

    float lm = (t < len) ? sc[t] : -1e30f;
#pragma unroll
    for (int o = 16; o; o >>= 1) lm = fmaxf(lm, __shfl_xor_sync(0xffffffffu, lm, o));
    if (lane == 0) redw[w] = lm;
    __syncthreads();
    if (t == 0) {
        float m = redw[0];
#pragma unroll
        for (int i = 1; i < 8; i++) m = fmaxf(m, redw[i]);
        s_m = m;
    }
    __syncthreads();
    const float m = s_m;
    float ls = 0.f;
    if (t < len) {
        float p = __expf(sc[t] - m);
        sc[t] = p;
        ls = p;
    }
#pragma unroll
    for (int o = 16; o; o >>= 1) ls += __shfl_xor_sync(0xffffffffu, ls, o);
    if (lane == 0) redw[w] = ls;
    __syncthreads();
    if (t == 0) {
        float l = 0.f;
#pragma unroll
        for (int i = 0; i < 8; i++) l += redw[i];
        s_l = l;
    }
    __syncthreads();

    const float* vnew = g_qkv + b * QKVN + 8192 + h * 128;
    const float* vbasep = v_cache + (size_t)b * SS * (HH * 128) + h * 128;
    const int d = t & 127;
    const int half = t >> 7;
    float acc = 0.f;
#pragma unroll 8
    for (int sl = half; sl < len; sl += 2) {
        int s = s0 + sl;
        const float* vr = (s == pos) ? vnew : (vbasep + (size_t)s * 4096);
        acc += sc[sl] * vr[d];
    }
    red[t] = acc;
    __syncthreads();
    if (t < 128) g_pacc[(size_t)pidx * 128 + t] = red[t] + red[t + 128];
    if (t == 0) {
        g_pm[pidx] = m;
        g_pl[pidx] = s_l;
    }
}

// combine the <=8 chunk partials per (b,h) -> g_attn[b][h*VD+d]
__global__ void __launch_bounds__(128) attn_combine_kernel() {
    const int bh = blockIdx.x;
    const int d = threadIdx.x;
    float M = -1e30f;
#pragma unroll
    for (int c = 0; c < NCHUNK; c++) {
        float l = g_pl[bh * NCHUNK + c];
        if (l > 0.f) M = fmaxf(M, g_pm[bh * NCHUNK + c]);
    }
    float L = 0.f, o = 0.f;
#pragma unroll
    for (int c = 0; c < NCHUNK; c++) {
        float l = g_pl[bh * NCHUNK + c];
        if (l > 0.f) {
            float wgt = __expf(g_pm[bh * NCHUNK + c] - M);
            L += l * wgt;
            o += g_pacc[(size_t)(bh * NCHUNK + c) * 128 + d] * wgt;
        }
    }
    const int b = bh >> 5, h = bh & 31;
    g_attn[b * 4096 + h * 128 + d] = o / L;
}

// sum the SPLIT2 GEMM2 split-K partials -> final output (float4 vectorized)
__global__ void reduce_out_kernel(float* __restrict__ out) {
    int i = blockIdx.x * 256 + threadIdx.x;   // 32768 float4s
    const float4* p = (const float4*)g_p2;
    float4 s = p[i];
#pragma unroll
    for (int c = 1; c < SPLIT2; c++) {
        float4 v = p[(size_t)c * 32768 + i];
        s.x += v.x;
        s.y += v.y;
        s.z += v.z;
        s.w += v.w;
    }
    ((float4*)out)[i] = s;
}

extern "C" void kernel_launch(void* const* d_in, const int* in_sizes, int n_in,
                              void* d_out, int out_size) {
    const float* hs = (const float*)d_in[0];
    const int* positions = (const int*)d_in[1];
    const float* k_cache = (const float*)d_in[2];
    const float* v_cache = (const float*)d_in[3];
    const float* Wq = (const float*)d_in[4];
    const float* Wkv = (const float*)d_in[5];
    const float* Wo = (const float*)d_in[6];
    float* out = (float*)d_out;

    float* p1;
    cudaGetSymbolAddress((void**)&p1, g_p1);
    float* p2;
    cudaGetSymbolAddress((void**)&p2, g_p2);

    // slot 1: prep (zero attention stats)
    prep_kernel<<<32, 256>>>();
    // slot 2: fused q(nope)/k/v projection: 48 N-tiles x split-K 16 (8 k-steps)
    gemm_kernel<0><<<dim3(48, SPLIT1), 256>>>(hs, Wq, Wkv, QKVN, 8, p1);
    // slot 3: split-K reduce -> g_qkv
    reduce_qkv_kernel<<<384, 256>>>();
    // slot 4 (ncu-profiled): flash-decoding attention partials
    attn_partial_kernel<<<dim3(1024, NCHUNK), 256>>>(k_cache, v_cache, positions);
    // slot 5: combine chunk partials
    attn_combine_kernel<<<1024, 128>>>();
    // slot 6: output projection: 16 N-tiles x split-K 16 (8 k-steps)
    gemm_kernel<1><<<dim3(16, SPLIT2), 256>>>(nullptr, Wo, nullptr, HID, 8, p2);
    // slot 7: final split-K reduce -> out
    reduce_out_kernel<<<128, 256>>>(out);
}